// round 6
// baseline (speedup 1.0000x reference)
#include <cuda_runtime.h>
#include <cuda_fp16.h>
#include <math.h>
#include <cstdint>

// ---------------------------------------------------------------------------
// Problem constants
// ---------------------------------------------------------------------------
#define NB   32
#define PP   1024
#define C0   64
#define KNN  16
#define NPTS (NB * PP)       // 32768
#define ROWS (NPTS * KNN)    // 524288
#define LRELU_ALPHA 0.1f
#define BN_EPS 1e-3f

// ---------------------------------------------------------------------------
// Static device scratch
// ---------------------------------------------------------------------------
__device__ float  d_A  [NPTS * 128];     // features @ (W0[:64]-W0[64:])
__device__ float  d_B  [NPTS * 128];     // features @ W0[64:]
__device__ float  d_SC [NPTS * 256];     // features @ Wsc (pre-BN)
__device__ __half d_y1 [ROWS * 128];     // y1 (pre-BN, fp16)
__device__ __half d_y2 [(size_t)ROWS * 256];  // y2 (pre-BN, fp16)
__device__ int    d_idx [ROWS];
__device__ float  d_sum  [4 * 256];
__device__ float  d_sumsq[4 * 256];

__device__ __forceinline__ void mma_f16(float* d, const uint32_t* a, const uint32_t* b) {
    asm volatile(
        "mma.sync.aligned.m16n8k16.row.col.f32.f16.f16.f32 "
        "{%0,%1,%2,%3}, {%4,%5,%6,%7}, {%8,%9}, {%0,%1,%2,%3};"
        : "+f"(d[0]), "+f"(d[1]), "+f"(d[2]), "+f"(d[3])
        : "r"(a[0]), "r"(a[1]), "r"(a[2]), "r"(a[3]), "r"(b[0]), "r"(b[1]));
}
__device__ __forceinline__ void ldmatrix_x4(uint32_t* r, uint32_t addr) {
    asm volatile("ldmatrix.sync.aligned.m8n8.x4.shared.b16 {%0,%1,%2,%3}, [%4];"
                 : "=r"(r[0]), "=r"(r[1]), "=r"(r[2]), "=r"(r[3]) : "r"(addr));
}
__device__ __forceinline__ uint32_t smem_u32(const void* p) {
    uint32_t a;
    asm("{ .reg .u64 t; cvta.to.shared.u64 t, %1; cvt.u32.u64 %0, t; }" : "=r"(a) : "l"(p));
    return a;
}
__device__ __forceinline__ uint32_t pack_h2(float lo, float hi) {
    __half2 h = __floats2half2_rn(lo, hi);
    return *(uint32_t*)&h;
}
__device__ __forceinline__ float lrelu(float x) {
    return x > 0.f ? x : LRELU_ALPHA * x;
}

// ---------------------------------------------------------------------------
// KNN (+ zero stats from block 0): 16 nearest excluding self
// ---------------------------------------------------------------------------
__global__ void knn_kernel(const float* __restrict__ pts) {
    if (blockIdx.x == 0) {
        for (int i = threadIdx.x; i < 1024; i += 256) {
            d_sum[i] = 0.f; d_sumsq[i] = 0.f;
        }
    }
    __shared__ float sx[PP], sy[PP], sz[PP];
    int n = blockIdx.x >> 2;
    int p = ((blockIdx.x & 3) << 8) + threadIdx.x;
    const float* base = pts + (size_t)n * PP * 3;
    for (int i = threadIdx.x; i < PP; i += blockDim.x) {
        sx[i] = base[i * 3 + 0];
        sy[i] = base[i * 3 + 1];
        sz[i] = base[i * 3 + 2];
    }
    __syncthreads();
    float qx = sx[p], qy = sy[p], qz = sz[p];
    float bd[KNN]; int bi[KNN];
#pragma unroll
    for (int i = 0; i < KNN; i++) { bd[i] = 3.0e38f; bi[i] = 0; }
    for (int q = 0; q < PP; q++) {
        float dx = sx[q] - qx, dy = sy[q] - qy, dz = sz[q] - qz;
        float d = dx * dx + dy * dy + dz * dz;
        if (q == p) continue;
        if (d < bd[KNN - 1]) {
            int j = KNN - 1;
            while (j > 0 && bd[j - 1] > d) { bd[j] = bd[j - 1]; bi[j] = bi[j - 1]; j--; }
            bd[j] = d; bi[j] = q;
        }
    }
    int ob = (n * PP + p) * KNN;
    for (int k = 0; k < KNN; k++) d_idx[ob + k] = bi[k];
}

// ---------------------------------------------------------------------------
// SIMT fp32 GEMM (feature matmuls, M=32768, K=64).
// DUAL: grid.y=0 -> A = f @ (W0[:64]-W0[64:]) (WA folded into the B load)
//       grid.y=1 -> B = f @ W0[64:]
// !DUAL: shortcut SC = f @ Wsc (N=256) with BN stats -> layer 3
// ---------------------------------------------------------------------------
#define GBM 128
#define GBN 128
#define GBK 8
template <bool STATS, bool DUAL>
__global__ void gemm_kernel(const float* __restrict__ X, const float* __restrict__ W_,
                            float* __restrict__ Y_, int Kc, int N,
                            float* __restrict__ Y2_,
                            float* sumArr, float* sumsqArr) {
    float* Y = Y_;
    int colBase = blockIdx.y * GBN;
    if (DUAL) {
        if (blockIdx.y == 1) Y = Y2_;
        colBase = 0;
    }
    __shared__ float As[GBK][GBM];
    __shared__ float Bs[GBK][GBN];
    int tid = threadIdx.x;
    int rowBase = blockIdx.x * GBM;
    int tx = tid & 15, ty = tid >> 4;
    float acc[8][8];
#pragma unroll
    for (int i = 0; i < 8; i++)
#pragma unroll
        for (int j = 0; j < 8; j++) acc[i][j] = 0.f;
    int a_row = tid >> 1, a_k4 = (tid & 1) * 4;
    int b_k = tid >> 5, b_n = (tid & 31) * 4;
    for (int k0 = 0; k0 < Kc; k0 += GBK) {
        float4 av = *(const float4*)&X[(size_t)(rowBase + a_row) * Kc + k0 + a_k4];
        As[a_k4 + 0][a_row] = av.x; As[a_k4 + 1][a_row] = av.y;
        As[a_k4 + 2][a_row] = av.z; As[a_k4 + 3][a_row] = av.w;
        float4 bv;
        if (DUAL) {
            // W_ = W0 ([128,128]); row k of WA = W0[k] - W0[64+k]
            float4 bhi = *(const float4*)&W_[(size_t)(64 + k0 + b_k) * 128 + b_n];
            if (blockIdx.y == 0) {
                float4 blo = *(const float4*)&W_[(size_t)(k0 + b_k) * 128 + b_n];
                bv.x = blo.x - bhi.x; bv.y = blo.y - bhi.y;
                bv.z = blo.z - bhi.z; bv.w = blo.w - bhi.w;
            } else bv = bhi;
        } else {
            bv = *(const float4*)&W_[(size_t)(k0 + b_k) * N + colBase + b_n];
        }
        *(float4*)&Bs[b_k][b_n] = bv;
        __syncthreads();
#pragma unroll
        for (int kk = 0; kk < GBK; kk++) {
            float4 a0 = *(const float4*)&As[kk][ty * 8];
            float4 a1 = *(const float4*)&As[kk][ty * 8 + 4];
            float4 b0 = *(const float4*)&Bs[kk][tx * 8];
            float4 b1 = *(const float4*)&Bs[kk][tx * 8 + 4];
            float a[8] = {a0.x, a0.y, a0.z, a0.w, a1.x, a1.y, a1.z, a1.w};
            float b[8] = {b0.x, b0.y, b0.z, b0.w, b1.x, b1.y, b1.z, b1.w};
#pragma unroll
            for (int i = 0; i < 8; i++)
#pragma unroll
                for (int j = 0; j < 8; j++) acc[i][j] += a[i] * b[j];
        }
        __syncthreads();
    }
#pragma unroll
    for (int i = 0; i < 8; i++) {
        int row = rowBase + ty * 8 + i;
        float4 c0 = {acc[i][0], acc[i][1], acc[i][2], acc[i][3]};
        float4 c1 = {acc[i][4], acc[i][5], acc[i][6], acc[i][7]};
        *(float4*)&Y[(size_t)row * N + colBase + tx * 8]     = c0;
        *(float4*)&Y[(size_t)row * N + colBase + tx * 8 + 4] = c1;
    }
    if constexpr (STATS) {
        __shared__ float ssum[GBN], ssq[GBN];
        if (tid < GBN) { ssum[tid] = 0.f; ssq[tid] = 0.f; }
        __syncthreads();
#pragma unroll
        for (int j = 0; j < 8; j++) {
            float s = 0.f, q = 0.f;
#pragma unroll
            for (int i = 0; i < 8; i++) { s += acc[i][j]; q += acc[i][j] * acc[i][j]; }
            atomicAdd(&ssum[tx * 8 + j], s);
            atomicAdd(&ssq [tx * 8 + j], q);
        }
        __syncthreads();
        if (tid < GBN) {
            atomicAdd(&sumArr  [colBase + tid], ssum[tid]);
            atomicAdd(&sumsqArr[colBase + tid], ssq[tid]);
        }
    }
}

// ---------------------------------------------------------------------------
// Layer-0 BN stats without materializing y0: y0 = A[np] + B[idx]
// Fixed geometry: 2048 blocks x 256 thr, 32 iterations, unroll 4 for MLP.
// ---------------------------------------------------------------------------
__global__ void __launch_bounds__(256) l0_stats_kernel() {
    const float4* A4 = (const float4*)d_A;
    const float4* B4 = (const float4*)d_B;
    __shared__ float ssum[128], ssq[128];
    if (threadIdx.x < 128) { ssum[threadIdx.x] = 0.f; ssq[threadIdx.x] = 0.f; }
    __syncthreads();
    const int start = blockIdx.x * 256 + threadIdx.x;
    const int c4 = start & 31;
    float s0 = 0, s1 = 0, s2 = 0, s3 = 0;
    float q0 = 0, q1 = 0, q2 = 0, q3 = 0;
#pragma unroll 4
    for (int i = 0; i < 32; i++) {
        int e = start + i * 524288;
        int r = e >> 5, cc = e & 31;
        int np = r >> 4, n = np >> 10;
        int id = __ldg(&d_idx[r]);
        float4 a = A4[np * 32 + cc];
        float4 b = B4[(n * 1024 + id) * 32 + cc];
        float yx = a.x + b.x, yy = a.y + b.y, yz = a.z + b.z, yw = a.w + b.w;
        s0 += yx; q0 += yx * yx; s1 += yy; q1 += yy * yy;
        s2 += yz; q2 += yz * yz; s3 += yw; q3 += yw * yw;
    }
    atomicAdd(&ssum[c4 * 4 + 0], s0); atomicAdd(&ssq[c4 * 4 + 0], q0);
    atomicAdd(&ssum[c4 * 4 + 1], s1); atomicAdd(&ssq[c4 * 4 + 1], q1);
    atomicAdd(&ssum[c4 * 4 + 2], s2); atomicAdd(&ssq[c4 * 4 + 2], q2);
    atomicAdd(&ssum[c4 * 4 + 3], s3); atomicAdd(&ssq[c4 * 4 + 3], q3);
    __syncthreads();
    if (threadIdx.x < 128) {
        atomicAdd(&d_sum  [threadIdx.x], ssum[threadIdx.x]);
        atomicAdd(&d_sumsq[threadIdx.x], ssq[threadIdx.x]);
    }
}

// ---------------------------------------------------------------------------
// fp16 mma GEMM with ldmatrix, K=128 one-shot, BN stats in epilogue,
// BN(layer_in) finalize inlined (scale/shift computed from global sums).
// N_TOT=128 (MODE 0, layer1): 256 thr, 8 warps (4x2), occ 2.
// N_TOT=256 (MODE 1, layer2): 512 thr, 16 warps (4x4), occ 1.
// ---------------------------------------------------------------------------
#define KW 68
template <int N_TOT, int MODE>
__global__ void __launch_bounds__(N_TOT * 2, MODE == 0 ? 2 : 1) gemm_mma_kernel(
    const __half* __restrict__ Xin, const float* __restrict__ W,
    __half* __restrict__ Y, const float* __restrict__ g, const float* __restrict__ b) {
    constexpr int THREADS = N_TOT * 2;
    constexpr int LAYER_IN  = MODE;          // 0 or 1
    constexpr int LAYER_OUT = MODE + 1;      // 1 or 2
    extern __shared__ char smem_raw[];
    uint32_t* As = (uint32_t*)smem_raw;                    // [128][KW]
    uint32_t* Bs = As + 128 * KW;                          // [N_TOT][KW]
    float*  ssum = (float*)(Bs + N_TOT * KW);              // [N_TOT]
    float*  ssq  = ssum + N_TOT;                           // [N_TOT]
    float*  scs  = ssq + N_TOT;                            // [128]
    float*  shs  = scs + 128;                              // [128]

    const int tid = threadIdx.x;
    const int wid = tid >> 5;
    const int lane = tid & 31;
    const int gid = lane >> 2;
    const int tg  = lane & 3;
    const int warpRow = wid & 3;
    const int warpCol = wid >> 2;
    const int tileBase = blockIdx.x * 128;

    // inline finalize of BN(layer_in)
    if (tid < 128) {
        float mean = d_sum[LAYER_IN * 256 + tid] * (1.0f / (float)ROWS);
        float var  = d_sumsq[LAYER_IN * 256 + tid] * (1.0f / (float)ROWS) - mean * mean;
        float sc = g[tid] * rsqrtf(var + BN_EPS);
        scs[tid] = sc;
        shs[tid] = b[tid] - mean * sc;
    }
    for (int c = tid; c < N_TOT; c += THREADS) { ssum[c] = 0.f; ssq[c] = 0.f; }
    __syncthreads();

    // ---- B tile: Bs[n][kw] = half2(W[2kw][n], W[2kw+1][n]) -----------------
    for (int e = tid; e < N_TOT * 64; e += THREADS) {
        int n = e & (N_TOT - 1), kw = e / N_TOT;
        float w0 = W[(size_t)(2 * kw)     * N_TOT + n];
        float w1 = W[(size_t)(2 * kw + 1) * N_TOT + n];
        Bs[n * KW + kw] = pack_h2(w0, w1);
    }

    // ---- A tile (fused gather/BN/lrelu producer) ---------------------------
    const float4* sc4 = (const float4*)scs;
    const float4* sh4 = (const float4*)shs;
    for (int e = tid; e < 128 * 16; e += THREADS) {
        int r = e >> 4, cw = e & 15;
        int R = tileBase + r;
        float x[8];
        if (MODE == 0) {
            int np = R >> 4, n = np >> 10;
            int id = d_idx[R];
            float4 a0 = ((const float4*)d_A)[np * 32 + cw * 2];
            float4 a1 = ((const float4*)d_A)[np * 32 + cw * 2 + 1];
            float4 b0 = ((const float4*)d_B)[(n * 1024 + id) * 32 + cw * 2];
            float4 b1 = ((const float4*)d_B)[(n * 1024 + id) * 32 + cw * 2 + 1];
            x[0] = a0.x + b0.x; x[1] = a0.y + b0.y; x[2] = a0.z + b0.z; x[3] = a0.w + b0.w;
            x[4] = a1.x + b1.x; x[5] = a1.y + b1.y; x[6] = a1.z + b1.z; x[7] = a1.w + b1.w;
        } else {
            uint4 h = ((const uint4*)&Xin[(size_t)R * 128])[cw];
            uint32_t hw[4] = {h.x, h.y, h.z, h.w};
#pragma unroll
            for (int j = 0; j < 4; j++) {
                float2 f = __half22float2(*(__half2*)&hw[j]);
                x[j * 2] = f.x; x[j * 2 + 1] = f.y;
            }
        }
        float4 sca = sc4[cw * 2], scb = sc4[cw * 2 + 1];
        float4 sha = sh4[cw * 2], shb = sh4[cw * 2 + 1];
        float y[8];
        y[0] = lrelu(x[0] * sca.x + sha.x); y[1] = lrelu(x[1] * sca.y + sha.y);
        y[2] = lrelu(x[2] * sca.z + sha.z); y[3] = lrelu(x[3] * sca.w + sha.w);
        y[4] = lrelu(x[4] * scb.x + shb.x); y[5] = lrelu(x[5] * scb.y + shb.y);
        y[6] = lrelu(x[6] * scb.z + shb.z); y[7] = lrelu(x[7] * scb.w + shb.w);
        uint32_t* dst = &As[r * KW + cw * 4];
        dst[0] = pack_h2(y[0], y[1]); dst[1] = pack_h2(y[2], y[3]);
        dst[2] = pack_h2(y[4], y[5]); dst[3] = pack_h2(y[6], y[7]);
    }
    __syncthreads();

    // ---- ldmatrix base addresses (k-step 0), advance 32B per k-step --------
    const int t8 = lane >> 3, r8 = lane & 7;
    uint32_t aAddr[2], bAddr[4];
#pragma unroll
    for (int mi = 0; mi < 2; mi++) {
        int row = warpRow * 32 + mi * 16 + (t8 & 1) * 8 + r8;
        aAddr[mi] = smem_u32(&As[row * KW + (t8 >> 1) * 4]);
    }
#pragma unroll
    for (int nj = 0; nj < 4; nj++) {
        int row = warpCol * 64 + nj * 16 + (t8 >> 1) * 8 + r8;
        bAddr[nj] = smem_u32(&Bs[row * KW + (t8 & 1) * 4]);
    }

    // ---- MMA main: warp tile 32x64, 8 K-steps of k16 -----------------------
    float c[2][8][4];
#pragma unroll
    for (int mi = 0; mi < 2; mi++)
#pragma unroll
        for (int ni = 0; ni < 8; ni++)
#pragma unroll
            for (int j = 0; j < 4; j++) c[mi][ni][j] = 0.f;

#pragma unroll
    for (int k0 = 0; k0 < 8; k0++) {
        uint32_t af[2][4], bf[4][4];
#pragma unroll
        for (int mi = 0; mi < 2; mi++) ldmatrix_x4(af[mi], aAddr[mi] + k0 * 32);
#pragma unroll
        for (int nj = 0; nj < 4; nj++) ldmatrix_x4(bf[nj], bAddr[nj] + k0 * 32);
#pragma unroll
        for (int mi = 0; mi < 2; mi++)
#pragma unroll
            for (int nj = 0; nj < 4; nj++) {
                mma_f16(c[mi][nj * 2],     af[mi], &bf[nj][0]);
                mma_f16(c[mi][nj * 2 + 1], af[mi], &bf[nj][2]);
            }
    }

    // ---- Epilogue: store fp16 y, accumulate stats --------------------------
#pragma unroll
    for (int mi = 0; mi < 2; mi++) {
        size_t r0 = (size_t)tileBase + warpRow * 32 + mi * 16 + gid;
#pragma unroll
        for (int ni = 0; ni < 8; ni++) {
            int col = warpCol * 64 + ni * 8 + tg * 2;
            __half2 v0 = __floats2half2_rn(c[mi][ni][0], c[mi][ni][1]);
            __half2 v1 = __floats2half2_rn(c[mi][ni][2], c[mi][ni][3]);
            *(__half2*)&Y[ r0      * N_TOT + col] = v0;
            *(__half2*)&Y[(r0 + 8) * N_TOT + col] = v1;
        }
    }
#pragma unroll
    for (int ni = 0; ni < 8; ni++) {
#pragma unroll
        for (int j = 0; j < 2; j++) {
            float s = c[0][ni][j] + c[0][ni][j + 2] + c[1][ni][j] + c[1][ni][j + 2];
            float q = c[0][ni][j]     * c[0][ni][j]
                    + c[0][ni][j + 2] * c[0][ni][j + 2]
                    + c[1][ni][j]     * c[1][ni][j]
                    + c[1][ni][j + 2] * c[1][ni][j + 2];
#pragma unroll
            for (int m = 16; m >= 4; m >>= 1) {
                s += __shfl_xor_sync(0xffffffffu, s, m);
                q += __shfl_xor_sync(0xffffffffu, q, m);
            }
            if (lane < 4) {
                int cch = warpCol * 64 + ni * 8 + tg * 2 + j;
                atomicAdd(&ssum[cch], s);
                atomicAdd(&ssq [cch], q);
            }
        }
    }
    __syncthreads();
    for (int c2 = tid; c2 < N_TOT; c2 += THREADS) {
        atomicAdd(&d_sum  [LAYER_OUT * 256 + c2], ssum[c2]);
        atomicAdd(&d_sumsq[LAYER_OUT * 256 + c2], ssq[c2]);
    }
}

// ---------------------------------------------------------------------------
// Final epilogue with inline finalize of BN2 (layer 2) and BN_sc (layer 3):
// out = lrelu( BN_sc(SC) + mean_k lrelu(BN2(y2)) )
// ---------------------------------------------------------------------------
__global__ void __launch_bounds__(256) final_kernel(
    float* __restrict__ out,
    const float* __restrict__ g2, const float* __restrict__ b2,
    const float* __restrict__ gsc, const float* __restrict__ bsc) {
    __shared__ float s2s[256], h2s[256], s3s[256], h3s[256];
    {
        int c = threadIdx.x;
        float mean2 = d_sum[2 * 256 + c] * (1.0f / (float)ROWS);
        float var2  = d_sumsq[2 * 256 + c] * (1.0f / (float)ROWS) - mean2 * mean2;
        float sc2 = g2[c] * rsqrtf(var2 + BN_EPS);
        s2s[c] = sc2; h2s[c] = b2[c] - mean2 * sc2;
        float mean3 = d_sum[3 * 256 + c] * (1.0f / (float)NPTS);
        float var3  = d_sumsq[3 * 256 + c] * (1.0f / (float)NPTS) - mean3 * mean3;
        float sc3 = gsc[c] * rsqrtf(var3 + BN_EPS);
        s3s[c] = sc3; h3s[c] = bsc[c] - mean3 * sc3;
    }
    __syncthreads();
    int t = blockIdx.x * blockDim.x + threadIdx.x;
    int np = t >> 6, c4 = t & 63;
    float4 s2 = *(const float4*)&s2s[c4 * 4];
    float4 h2 = *(const float4*)&h2s[c4 * 4];
    float4 s3 = *(const float4*)&s3s[c4 * 4];
    float4 h3 = *(const float4*)&h3s[c4 * 4];
    const uint2* Y2 = (const uint2*)d_y2;
    size_t base = (size_t)np * 16 * 64 + c4;
    float ax = 0, ay = 0, az = 0, aw = 0;
#pragma unroll
    for (int k = 0; k < KNN; k++) {
        uint2 hv = Y2[base + (size_t)k * 64];
        float2 f01 = __half22float2(*(__half2*)&hv.x);
        float2 f23 = __half22float2(*(__half2*)&hv.y);
        ax += lrelu(f01.x * s2.x + h2.x);
        ay += lrelu(f01.y * s2.y + h2.y);
        az += lrelu(f23.x * s2.z + h2.z);
        aw += lrelu(f23.y * s2.w + h2.w);
    }
    const float inv = 1.0f / (float)KNN;
    float4 s = ((const float4*)d_SC)[np * 64 + c4];
    float4 o;
    o.x = lrelu(s.x * s3.x + h3.x + ax * inv);
    o.y = lrelu(s.y * s3.y + h3.y + ay * inv);
    o.z = lrelu(s.z * s3.z + h3.z + az * inv);
    o.w = lrelu(s.w * s3.w + h3.w + aw * inv);
    ((float4*)out)[t] = o;
}

// ---------------------------------------------------------------------------
// Launch (7 launches; mma1 at index 3 -> ncu abs index 5)
// ---------------------------------------------------------------------------
extern "C" void kernel_launch(void* const* d_in, const int* in_sizes, int n_in,
                              void* d_out, int out_size) {
    const float* points   = (const float*)d_in[0];
    const float* features = (const float*)d_in[1];
    const float* W0  = (const float*)d_in[2];
    const float* g0  = (const float*)d_in[3];
    const float* b0  = (const float*)d_in[4];
    const float* W1  = (const float*)d_in[5];
    const float* g1  = (const float*)d_in[6];
    const float* b1  = (const float*)d_in[7];
    const float* W2  = (const float*)d_in[8];
    const float* g2  = (const float*)d_in[9];
    const float* b2  = (const float*)d_in[10];
    const float* Wsc = (const float*)d_in[11];
    const float* gsc = (const float*)d_in[12];
    const float* bsc = (const float*)d_in[13];
    float* out = (float*)d_out;

    float *pA, *pB, *pSC, *psum, *psq;
    __half *p1, *p2;
    cudaGetSymbolAddress((void**)&pA,  d_A);
    cudaGetSymbolAddress((void**)&pB,  d_B);
    cudaGetSymbolAddress((void**)&pSC, d_SC);
    cudaGetSymbolAddress((void**)&p1,  d_y1);
    cudaGetSymbolAddress((void**)&p2,  d_y2);
    cudaGetSymbolAddress((void**)&psum, d_sum);
    cudaGetSymbolAddress((void**)&psq,  d_sumsq);

    constexpr int SMEM_MMA1 = (128 * KW + 128 * KW) * 4 + (2 * 128 + 256) * 4;
    constexpr int SMEM_MMA2 = (128 * KW + 256 * KW) * 4 + (2 * 256 + 256) * 4;
    cudaFuncSetAttribute(gemm_mma_kernel<128, 0>,
                         cudaFuncAttributeMaxDynamicSharedMemorySize, SMEM_MMA1);
    cudaFuncSetAttribute(gemm_mma_kernel<256, 1>,
                         cudaFuncAttributeMaxDynamicSharedMemorySize, SMEM_MMA2);

    // 0: knn (+ zero stats)
    knn_kernel<<<128, 256>>>(points);
    // 1: A = f@(W0lo-W0hi), B = f@W0hi (dual)
    gemm_kernel<false, true><<<dim3(NPTS / GBM, 2), 256>>>(
        features, W0, pA, 64, 128, pB, nullptr, nullptr);
    // 2: layer-0 stats (virtual y0)
    l0_stats_kernel<<<2048, 256>>>();
    // 3: layer-1 MMA (gather+BN0+lrelu fused; BN0 finalize inline)
    gemm_mma_kernel<128, 0><<<ROWS / 128, 256, SMEM_MMA1>>>(nullptr, W1, p1, g0, b0);
    // 4: shortcut SC = f @ Wsc (+ stats -> layer 3)
    gemm_kernel<true, false><<<dim3(NPTS / GBM, 2), 256>>>(
        features, Wsc, pSC, 64, 256, nullptr, psum + 3 * 256, psq + 3 * 256);
    // 5: layer-2 MMA (BN1+lrelu fused; BN1 finalize inline; full N=256)
    gemm_mma_kernel<256, 1><<<ROWS / 128, 512, SMEM_MMA2>>>(p1, W2, p2, g1, b1);
    // 6: final epilogue (BN2 + BN_sc finalize inline)
    final_kernel<<<NPTS * 64 / 256, 256>>>(out, g2, b2, gsc, bsc);
}

// round 8
// speedup vs baseline: 1.2350x; 1.2350x over previous
#include <cuda_runtime.h>
#include <cuda_fp16.h>
#include <math.h>
#include <cstdint>

// ---------------------------------------------------------------------------
// Problem constants
// ---------------------------------------------------------------------------
#define NB   32
#define PP   1024
#define C0   64
#define KNN  16
#define NPTS (NB * PP)       // 32768
#define ROWS (NPTS * KNN)    // 524288
#define LRELU_ALPHA 0.1f
#define BN_EPS 1e-3f

// ---------------------------------------------------------------------------
// Static device scratch
// ---------------------------------------------------------------------------
__device__ __half d_Ah [NPTS * 128];     // features @ (W0[:64]-W0[64:])  (fp16)
__device__ __half d_Bh [NPTS * 128];     // features @ W0[64:]            (fp16)
__device__ float  d_SC [NPTS * 256];     // features @ Wsc (pre-BN, fp32)
__device__ __half d_y1 [ROWS * 128];     // y1 (pre-BN, fp16)
__device__ __half d_y2 [(size_t)ROWS * 256];  // y2 (pre-BN, fp16)
__device__ int    d_idx [ROWS];
__device__ uint32_t d_W1t[128 * 64];     // W1 as [n][kw] packed half2
__device__ uint32_t d_W2t[256 * 64];     // W2 as [n][kw] packed half2
__device__ float  d_sum  [4 * 256];
__device__ float  d_sumsq[4 * 256];

__device__ __forceinline__ void mma_f16(float* d, const uint32_t* a, const uint32_t* b) {
    asm volatile(
        "mma.sync.aligned.m16n8k16.row.col.f32.f16.f16.f32 "
        "{%0,%1,%2,%3}, {%4,%5,%6,%7}, {%8,%9}, {%0,%1,%2,%3};"
        : "+f"(d[0]), "+f"(d[1]), "+f"(d[2]), "+f"(d[3])
        : "r"(a[0]), "r"(a[1]), "r"(a[2]), "r"(a[3]), "r"(b[0]), "r"(b[1]));
}
__device__ __forceinline__ void ldmatrix_x4(uint32_t* r, uint32_t addr) {
    asm volatile("ldmatrix.sync.aligned.m8n8.x4.shared.b16 {%0,%1,%2,%3}, [%4];"
                 : "=r"(r[0]), "=r"(r[1]), "=r"(r[2]), "=r"(r[3]) : "r"(addr));
}
__device__ __forceinline__ uint32_t smem_u32(const void* p) {
    uint32_t a;
    asm("{ .reg .u64 t; cvta.to.shared.u64 t, %1; cvt.u32.u64 %0, t; }" : "=r"(a) : "l"(p));
    return a;
}
__device__ __forceinline__ uint32_t pack_h2(float lo, float hi) {
    __half2 h = __floats2half2_rn(lo, hi);
    return *(uint32_t*)&h;
}
__device__ __forceinline__ float lrelu(float x) {
    return x > 0.f ? x : LRELU_ALPHA * x;
}

// ---------------------------------------------------------------------------
// KNN (+ stats zeroing from block 0, W1/W2 fp16-transpose from blocks 1-3)
// ---------------------------------------------------------------------------
__global__ void knn_kernel(const float* __restrict__ pts,
                           const float* __restrict__ W1,
                           const float* __restrict__ W2) {
    if (blockIdx.x == 0) {
        for (int i = threadIdx.x; i < 1024; i += 256) {
            d_sum[i] = 0.f; d_sumsq[i] = 0.f;
        }
    } else if (blockIdx.x == 1) {
        for (int t = threadIdx.x; t < 128 * 64; t += 256) {
            int n = t >> 6, kw = t & 63;
            d_W1t[t] = pack_h2(W1[(size_t)(2 * kw) * 128 + n],
                               W1[(size_t)(2 * kw + 1) * 128 + n]);
        }
    } else if (blockIdx.x <= 3) {
        int base = (blockIdx.x - 2) * 8192;
        for (int i = threadIdx.x; i < 8192; i += 256) {
            int t = base + i;
            int n = t >> 6, kw = t & 63;
            d_W2t[t] = pack_h2(W2[(size_t)(2 * kw) * 256 + n],
                               W2[(size_t)(2 * kw + 1) * 256 + n]);
        }
    }
    __shared__ float sx[PP], sy[PP], sz[PP];
    int n = blockIdx.x >> 2;
    int p = ((blockIdx.x & 3) << 8) + threadIdx.x;
    const float* base = pts + (size_t)n * PP * 3;
    for (int i = threadIdx.x; i < PP; i += blockDim.x) {
        sx[i] = base[i * 3 + 0];
        sy[i] = base[i * 3 + 1];
        sz[i] = base[i * 3 + 2];
    }
    __syncthreads();
    float qx = sx[p], qy = sy[p], qz = sz[p];
    float bd[KNN]; int bi[KNN];
#pragma unroll
    for (int i = 0; i < KNN; i++) { bd[i] = 3.0e38f; bi[i] = 0; }
    for (int q = 0; q < PP; q++) {
        float dx = sx[q] - qx, dy = sy[q] - qy, dz = sz[q] - qz;
        float d = dx * dx + dy * dy + dz * dz;
        if (q == p) continue;
        if (d < bd[KNN - 1]) {
            int j = KNN - 1;
            while (j > 0 && bd[j - 1] > d) { bd[j] = bd[j - 1]; bi[j] = bi[j - 1]; j--; }
            bd[j] = d; bi[j] = q;
        }
    }
    int ob = (n * PP + p) * KNN;
    for (int k = 0; k < KNN; k++) d_idx[ob + k] = bi[k];
}

// ---------------------------------------------------------------------------
// SIMT fp32 GEMM (feature matmuls, M=32768, K=64).
// DUAL: grid.y=0 -> A = f @ (W0[:64]-W0[64:]), grid.y=1 -> B = f @ W0[64:];
//       output fp16.
// !DUAL: shortcut SC = f @ Wsc (N=256) fp32 out, with BN stats -> layer 3
// ---------------------------------------------------------------------------
#define GBM 128
#define GBN 128
#define GBK 8
template <bool STATS, bool DUAL>
__global__ void gemm_kernel(const float* __restrict__ X, const float* __restrict__ W_,
                            void* __restrict__ Y_, int Kc, int N,
                            void* __restrict__ Y2_,
                            float* sumArr, float* sumsqArr) {
    void* Yv = Y_;
    int colBase = blockIdx.y * GBN;
    if (DUAL) {
        if (blockIdx.y == 1) Yv = Y2_;
        colBase = 0;
    }
    __shared__ float As[GBK][GBM];
    __shared__ float Bs[GBK][GBN];
    int tid = threadIdx.x;
    int rowBase = blockIdx.x * GBM;
    int tx = tid & 15, ty = tid >> 4;
    float acc[8][8];
#pragma unroll
    for (int i = 0; i < 8; i++)
#pragma unroll
        for (int j = 0; j < 8; j++) acc[i][j] = 0.f;
    int a_row = tid >> 1, a_k4 = (tid & 1) * 4;
    int b_k = tid >> 5, b_n = (tid & 31) * 4;
    for (int k0 = 0; k0 < Kc; k0 += GBK) {
        float4 av = *(const float4*)&X[(size_t)(rowBase + a_row) * Kc + k0 + a_k4];
        As[a_k4 + 0][a_row] = av.x; As[a_k4 + 1][a_row] = av.y;
        As[a_k4 + 2][a_row] = av.z; As[a_k4 + 3][a_row] = av.w;
        float4 bv;
        if (DUAL) {
            float4 bhi = *(const float4*)&W_[(size_t)(64 + k0 + b_k) * 128 + b_n];
            if (blockIdx.y == 0) {
                float4 blo = *(const float4*)&W_[(size_t)(k0 + b_k) * 128 + b_n];
                bv.x = blo.x - bhi.x; bv.y = blo.y - bhi.y;
                bv.z = blo.z - bhi.z; bv.w = blo.w - bhi.w;
            } else bv = bhi;
        } else {
            bv = *(const float4*)&W_[(size_t)(k0 + b_k) * N + colBase + b_n];
        }
        *(float4*)&Bs[b_k][b_n] = bv;
        __syncthreads();
#pragma unroll
        for (int kk = 0; kk < GBK; kk++) {
            float4 a0 = *(const float4*)&As[kk][ty * 8];
            float4 a1 = *(const float4*)&As[kk][ty * 8 + 4];
            float4 b0 = *(const float4*)&Bs[kk][tx * 8];
            float4 b1 = *(const float4*)&Bs[kk][tx * 8 + 4];
            float a[8] = {a0.x, a0.y, a0.z, a0.w, a1.x, a1.y, a1.z, a1.w};
            float b[8] = {b0.x, b0.y, b0.z, b0.w, b1.x, b1.y, b1.z, b1.w};
#pragma unroll
            for (int i = 0; i < 8; i++)
#pragma unroll
                for (int j = 0; j < 8; j++) acc[i][j] += a[i] * b[j];
        }
        __syncthreads();
    }
    if (DUAL) {
        __half* Yh = (__half*)Yv;
#pragma unroll
        for (int i = 0; i < 8; i++) {
            int row = rowBase + ty * 8 + i;
            uint4 v;
            v.x = pack_h2(acc[i][0], acc[i][1]);
            v.y = pack_h2(acc[i][2], acc[i][3]);
            v.z = pack_h2(acc[i][4], acc[i][5]);
            v.w = pack_h2(acc[i][6], acc[i][7]);
            *(uint4*)&Yh[(size_t)row * 128 + tx * 8] = v;
        }
    } else {
        float* Y = (float*)Yv;
#pragma unroll
        for (int i = 0; i < 8; i++) {
            int row = rowBase + ty * 8 + i;
            float4 c0 = {acc[i][0], acc[i][1], acc[i][2], acc[i][3]};
            float4 c1 = {acc[i][4], acc[i][5], acc[i][6], acc[i][7]};
            *(float4*)&Y[(size_t)row * N + colBase + tx * 8]     = c0;
            *(float4*)&Y[(size_t)row * N + colBase + tx * 8 + 4] = c1;
        }
    }
    if constexpr (STATS) {
        __shared__ float ssum[GBN], ssq[GBN];
        if (tid < GBN) { ssum[tid] = 0.f; ssq[tid] = 0.f; }
        __syncthreads();
#pragma unroll
        for (int j = 0; j < 8; j++) {
            float s = 0.f, q = 0.f;
#pragma unroll
            for (int i = 0; i < 8; i++) { s += acc[i][j]; q += acc[i][j] * acc[i][j]; }
            atomicAdd(&ssum[tx * 8 + j], s);
            atomicAdd(&ssq [tx * 8 + j], q);
        }
        __syncthreads();
        if (tid < GBN) {
            atomicAdd(&sumArr  [colBase + tid], ssum[tid]);
            atomicAdd(&sumsqArr[colBase + tid], ssq[tid]);
        }
    }
}

// ---------------------------------------------------------------------------
// Layer-0 BN stats without materializing y0: y0 = A[np] + B[idx]   (fp16 in)
// 2048 blocks x 256 thr; each thread: fixed 8-channel group, 16 iterations.
// ---------------------------------------------------------------------------
__global__ void __launch_bounds__(256) l0_stats_kernel() {
    const uint4* A4 = (const uint4*)d_Ah;   // 16 uint4 per row (128 ch fp16)
    const uint4* B4 = (const uint4*)d_Bh;
    __shared__ float ssum[128], ssq[128];
    if (threadIdx.x < 128) { ssum[threadIdx.x] = 0.f; ssq[threadIdx.x] = 0.f; }
    __syncthreads();
    const int start = blockIdx.x * 256 + threadIdx.x;   // 0..524287
    const int c8 = start & 15;
    float s[8], q[8];
#pragma unroll
    for (int j = 0; j < 8; j++) { s[j] = 0.f; q[j] = 0.f; }
#pragma unroll 4
    for (int i = 0; i < 16; i++) {
        int e = start + i * 524288;
        int r = e >> 4, cc = e & 15;
        int np = r >> 4, n = r >> 14;
        int id = __ldg(&d_idx[r]);
        uint4 a = A4[(size_t)np * 16 + cc];
        uint4 b = B4[((size_t)n * 1024 + id) * 16 + cc];
        uint32_t aw[4] = {a.x, a.y, a.z, a.w};
        uint32_t bw[4] = {b.x, b.y, b.z, b.w};
#pragma unroll
        for (int j = 0; j < 4; j++) {
            float2 fa = __half22float2(*(__half2*)&aw[j]);
            float2 fb = __half22float2(*(__half2*)&bw[j]);
            float y0 = fa.x + fb.x, y1 = fa.y + fb.y;
            s[j * 2]     += y0; q[j * 2]     += y0 * y0;
            s[j * 2 + 1] += y1; q[j * 2 + 1] += y1 * y1;
        }
    }
#pragma unroll
    for (int j = 0; j < 8; j++) {
        atomicAdd(&ssum[c8 * 8 + j], s[j]);
        atomicAdd(&ssq [c8 * 8 + j], q[j]);
    }
    __syncthreads();
    if (threadIdx.x < 128) {
        atomicAdd(&d_sum  [threadIdx.x], ssum[threadIdx.x]);
        atomicAdd(&d_sumsq[threadIdx.x], ssq[threadIdx.x]);
    }
}

// ---------------------------------------------------------------------------
// fp16 mma GEMM with ldmatrix: BM=128, BN=128 (column split for N=256),
// K=128 one-shot, 256 thr = 8 warps (4x2), warp tile 32x64, occ 2.
// MODE 0: A = lrelu(BN0(gather Ah+Bh)), Y = y1 [ROWS,128]
// MODE 1: A = lrelu(BN1(y1)),           Y = y2 [ROWS,256], blockIdx.y = N-half
// BN(layer_in) finalize inlined; BN stats of output accumulated in epilogue.
// ---------------------------------------------------------------------------
#define KW 68
template <int N_TOT, int MODE>
__global__ void __launch_bounds__(256, 2) gemm_mma_kernel(
    const __half* __restrict__ Xin, const uint32_t* __restrict__ Wt,
    __half* __restrict__ Y, const float* __restrict__ g, const float* __restrict__ b) {
    constexpr int LAYER_IN  = MODE;
    constexpr int LAYER_OUT = MODE + 1;
    extern __shared__ char smem_raw[];
    uint32_t* As = (uint32_t*)smem_raw;                    // [128][KW]
    uint32_t* Bs = As + 128 * KW;                          // [128][KW]
    float*  ssum = (float*)(Bs + 128 * KW);                // [128]
    float*  ssq  = ssum + 128;                             // [128]
    float*  scs  = ssq + 128;                              // [128]
    float*  shs  = scs + 128;                              // [128]

    const int tid = threadIdx.x;
    const int wid = tid >> 5;
    const int lane = tid & 31;
    const int gid = lane >> 2;
    const int tg  = lane & 3;
    const int warpRow = wid & 3;
    const int warpCol = wid >> 2;
    const int tileBase = blockIdx.x * 128;
    const int colBase  = (MODE == 1) ? blockIdx.y * 128 : 0;

    // inline finalize of BN(layer_in)
    if (tid < 128) {
        float mean = d_sum[LAYER_IN * 256 + tid] * (1.0f / (float)ROWS);
        float var  = d_sumsq[LAYER_IN * 256 + tid] * (1.0f / (float)ROWS) - mean * mean;
        float sc = g[tid] * rsqrtf(var + BN_EPS);
        scs[tid] = sc;
        shs[tid] = b[tid] - mean * sc;
        ssum[tid] = 0.f; ssq[tid] = 0.f;
    }
    __syncthreads();

    // ---- B tile: straight packed copy from pre-transposed Wt ---------------
    {
        const uint4* src = (const uint4*)(Wt + (size_t)colBase * 64);
#pragma unroll
        for (int i = 0; i < 8; i++) {
            int e4 = tid + i * 256;            // 2048 uint4s
            int n = e4 >> 4, kw4 = e4 & 15;
            *(uint4*)&Bs[n * KW + kw4 * 4] = src[e4];
        }
    }

    // ---- A tile (fused gather/BN/lrelu producer, fp16 inputs) --------------
    int ids[8];
    if (MODE == 0) {
#pragma unroll
        for (int i = 0; i < 8; i++) {
            int r = (tid + i * 256) >> 4;
            ids[i] = __ldg(&d_idx[tileBase + r]);
        }
    }
#pragma unroll
    for (int i = 0; i < 8; i++) {
        int e = tid + i * 256;
        int r = e >> 4, cw = e & 15;
        int R = tileBase + r;
        uint4 h;
        float x[8];
        if (MODE == 0) {
            int np = R >> 4, n = R >> 14;
            uint4 ha = ((const uint4*)d_Ah)[(size_t)np * 16 + cw];
            uint4 hb = ((const uint4*)d_Bh)[((size_t)n * 1024 + ids[i]) * 16 + cw];
            uint32_t aw[4] = {ha.x, ha.y, ha.z, ha.w};
            uint32_t bw[4] = {hb.x, hb.y, hb.z, hb.w};
#pragma unroll
            for (int j = 0; j < 4; j++) {
                float2 fa = __half22float2(*(__half2*)&aw[j]);
                float2 fb = __half22float2(*(__half2*)&bw[j]);
                x[j * 2] = fa.x + fb.x; x[j * 2 + 1] = fa.y + fb.y;
            }
        } else {
            h = ((const uint4*)&Xin[(size_t)R * 128])[cw];
            uint32_t hw[4] = {h.x, h.y, h.z, h.w};
#pragma unroll
            for (int j = 0; j < 4; j++) {
                float2 f = __half22float2(*(__half2*)&hw[j]);
                x[j * 2] = f.x; x[j * 2 + 1] = f.y;
            }
        }
        const float* sc = &scs[cw * 8];
        const float* sh = &shs[cw * 8];
        float y[8];
#pragma unroll
        for (int j = 0; j < 8; j++) y[j] = lrelu(x[j] * sc[j] + sh[j]);
        uint4 v;
        v.x = pack_h2(y[0], y[1]); v.y = pack_h2(y[2], y[3]);
        v.z = pack_h2(y[4], y[5]); v.w = pack_h2(y[6], y[7]);
        *(uint4*)&As[r * KW + cw * 4] = v;
    }
    __syncthreads();

    // ---- ldmatrix base addresses (k-step 0), advance 32B per k-step --------
    const int t8 = lane >> 3, r8 = lane & 7;
    uint32_t aAddr[2], bAddr[4];
#pragma unroll
    for (int mi = 0; mi < 2; mi++) {
        int row = warpRow * 32 + mi * 16 + (t8 & 1) * 8 + r8;
        aAddr[mi] = smem_u32(&As[row * KW + (t8 >> 1) * 4]);
    }
#pragma unroll
    for (int nj = 0; nj < 4; nj++) {
        int row = warpCol * 64 + nj * 16 + (t8 >> 1) * 8 + r8;
        bAddr[nj] = smem_u32(&Bs[row * KW + (t8 & 1) * 4]);
    }

    // ---- MMA main: warp tile 32x64, 8 K-steps of k16 -----------------------
    float c[2][8][4];
#pragma unroll
    for (int mi = 0; mi < 2; mi++)
#pragma unroll
        for (int ni = 0; ni < 8; ni++)
#pragma unroll
            for (int j = 0; j < 4; j++) c[mi][ni][j] = 0.f;

#pragma unroll
    for (int k0 = 0; k0 < 8; k0++) {
        uint32_t af[2][4], bf[4][4];
#pragma unroll
        for (int mi = 0; mi < 2; mi++) ldmatrix_x4(af[mi], aAddr[mi] + k0 * 32);
#pragma unroll
        for (int nj = 0; nj < 4; nj++) ldmatrix_x4(bf[nj], bAddr[nj] + k0 * 32);
#pragma unroll
        for (int mi = 0; mi < 2; mi++)
#pragma unroll
            for (int nj = 0; nj < 4; nj++) {
                mma_f16(c[mi][nj * 2],     af[mi], &bf[nj][0]);
                mma_f16(c[mi][nj * 2 + 1], af[mi], &bf[nj][2]);
            }
    }

    // ---- Epilogue: store fp16 y, accumulate stats --------------------------
#pragma unroll
    for (int mi = 0; mi < 2; mi++) {
        size_t r0 = (size_t)tileBase + warpRow * 32 + mi * 16 + gid;
#pragma unroll
        for (int ni = 0; ni < 8; ni++) {
            int col = colBase + warpCol * 64 + ni * 8 + tg * 2;
            __half2 v0 = __floats2half2_rn(c[mi][ni][0], c[mi][ni][1]);
            __half2 v1 = __floats2half2_rn(c[mi][ni][2], c[mi][ni][3]);
            *(__half2*)&Y[ r0      * N_TOT + col] = v0;
            *(__half2*)&Y[(r0 + 8) * N_TOT + col] = v1;
        }
    }
#pragma unroll
    for (int ni = 0; ni < 8; ni++) {
#pragma unroll
        for (int j = 0; j < 2; j++) {
            float s = c[0][ni][j] + c[0][ni][j + 2] + c[1][ni][j] + c[1][ni][j + 2];
            float q = c[0][ni][j]     * c[0][ni][j]
                    + c[0][ni][j + 2] * c[0][ni][j + 2]
                    + c[1][ni][j]     * c[1][ni][j]
                    + c[1][ni][j + 2] * c[1][ni][j + 2];
#pragma unroll
            for (int m = 16; m >= 4; m >>= 1) {
                s += __shfl_xor_sync(0xffffffffu, s, m);
                q += __shfl_xor_sync(0xffffffffu, q, m);
            }
            if (lane < 4) {
                int cch = warpCol * 64 + ni * 8 + tg * 2 + j;
                atomicAdd(&ssum[cch], s);
                atomicAdd(&ssq [cch], q);
            }
        }
    }
    __syncthreads();
    if (tid < 128) {
        atomicAdd(&d_sum  [LAYER_OUT * 256 + colBase + tid], ssum[tid]);
        atomicAdd(&d_sumsq[LAYER_OUT * 256 + colBase + tid], ssq[tid]);
    }
}

// ---------------------------------------------------------------------------
// Final epilogue with inline finalize of BN2 (layer 2) and BN_sc (layer 3):
// out = lrelu( BN_sc(SC) + mean_k lrelu(BN2(y2)) )
// ---------------------------------------------------------------------------
__global__ void __launch_bounds__(256) final_kernel(
    float* __restrict__ out,
    const float* __restrict__ g2, const float* __restrict__ b2,
    const float* __restrict__ gsc, const float* __restrict__ bsc) {
    __shared__ float s2s[256], h2s[256], s3s[256], h3s[256];
    {
        int c = threadIdx.x;
        float mean2 = d_sum[2 * 256 + c] * (1.0f / (float)ROWS);
        float var2  = d_sumsq[2 * 256 + c] * (1.0f / (float)ROWS) - mean2 * mean2;
        float sc2 = g2[c] * rsqrtf(var2 + BN_EPS);
        s2s[c] = sc2; h2s[c] = b2[c] - mean2 * sc2;
        float mean3 = d_sum[3 * 256 + c] * (1.0f / (float)NPTS);
        float var3  = d_sumsq[3 * 256 + c] * (1.0f / (float)NPTS) - mean3 * mean3;
        float sc3 = gsc[c] * rsqrtf(var3 + BN_EPS);
        s3s[c] = sc3; h3s[c] = bsc[c] - mean3 * sc3;
    }
    __syncthreads();
    int t = blockIdx.x * blockDim.x + threadIdx.x;
    int np = t >> 6, c4 = t & 63;
    float4 s2 = *(const float4*)&s2s[c4 * 4];
    float4 h2 = *(const float4*)&h2s[c4 * 4];
    float4 s3 = *(const float4*)&s3s[c4 * 4];
    float4 h3 = *(const float4*)&h3s[c4 * 4];
    const uint2* Y2 = (const uint2*)d_y2;
    size_t base = (size_t)np * 16 * 64 + c4;
    float ax = 0, ay = 0, az = 0, aw = 0;
#pragma unroll
    for (int k = 0; k < KNN; k++) {
        uint2 hv = Y2[base + (size_t)k * 64];
        float2 f01 = __half22float2(*(__half2*)&hv.x);
        float2 f23 = __half22float2(*(__half2*)&hv.y);
        ax += lrelu(f01.x * s2.x + h2.x);
        ay += lrelu(f01.y * s2.y + h2.y);
        az += lrelu(f23.x * s2.z + h2.z);
        aw += lrelu(f23.y * s2.w + h2.w);
    }
    const float inv = 1.0f / (float)KNN;
    float4 s = ((const float4*)d_SC)[np * 64 + c4];
    float4 o;
    o.x = lrelu(s.x * s3.x + h3.x + ax * inv);
    o.y = lrelu(s.y * s3.y + h3.y + ay * inv);
    o.z = lrelu(s.z * s3.z + h3.z + az * inv);
    o.w = lrelu(s.w * s3.w + h3.w + aw * inv);
    ((float4*)out)[t] = o;
}

// ---------------------------------------------------------------------------
// Launch (7 launches; mma1 at index 3 -> ncu abs index 5)
// ---------------------------------------------------------------------------
extern "C" void kernel_launch(void* const* d_in, const int* in_sizes, int n_in,
                              void* d_out, int out_size) {
    const float* points   = (const float*)d_in[0];
    const float* features = (const float*)d_in[1];
    const float* W0  = (const float*)d_in[2];
    const float* g0  = (const float*)d_in[3];
    const float* b0  = (const float*)d_in[4];
    const float* W1  = (const float*)d_in[5];
    const float* g1  = (const float*)d_in[6];
    const float* b1  = (const float*)d_in[7];
    const float* W2  = (const float*)d_in[8];
    const float* g2  = (const float*)d_in[9];
    const float* b2  = (const float*)d_in[10];
    const float* Wsc = (const float*)d_in[11];
    const float* gsc = (const float*)d_in[12];
    const float* bsc = (const float*)d_in[13];
    float* out = (float*)d_out;

    float *pSC, *psum, *psq;
    __half *pAh, *pBh, *p1, *p2;
    uint32_t *pW1t, *pW2t;
    cudaGetSymbolAddress((void**)&pAh, d_Ah);
    cudaGetSymbolAddress((void**)&pBh, d_Bh);
    cudaGetSymbolAddress((void**)&pSC, d_SC);
    cudaGetSymbolAddress((void**)&p1,  d_y1);
    cudaGetSymbolAddress((void**)&p2,  d_y2);
    cudaGetSymbolAddress((void**)&pW1t, d_W1t);
    cudaGetSymbolAddress((void**)&pW2t, d_W2t);
    cudaGetSymbolAddress((void**)&psum, d_sum);
    cudaGetSymbolAddress((void**)&psq,  d_sumsq);

    constexpr int SMEM_MMA = (2 * 128 * KW) * 4 + 4 * 128 * 4;   // ~71.7KB
    cudaFuncSetAttribute(gemm_mma_kernel<128, 0>,
                         cudaFuncAttributeMaxDynamicSharedMemorySize, SMEM_MMA);
    cudaFuncSetAttribute(gemm_mma_kernel<256, 1>,
                         cudaFuncAttributeMaxDynamicSharedMemorySize, SMEM_MMA);

    // 0: knn (+ zero stats + W1/W2 fp16 transpose)
    knn_kernel<<<128, 256>>>(points, W1, W2);
    // 1: A = f@(W0lo-W0hi), B = f@W0hi (dual, fp16 out)
    gemm_kernel<false, true><<<dim3(NPTS / GBM, 2), 256>>>(
        features, W0, pAh, 64, 128, pBh, nullptr, nullptr);
    // 2: layer-0 stats (virtual y0, fp16 in)
    l0_stats_kernel<<<2048, 256>>>();
    // 3: layer-1 MMA (gather+BN0+lrelu fused; BN0 finalize inline)
    gemm_mma_kernel<128, 0><<<dim3(ROWS / 128, 1), 256, SMEM_MMA>>>(
        nullptr, pW1t, p1, g0, b0);
    // 4: shortcut SC = f @ Wsc (+ stats -> layer 3)
    gemm_kernel<true, false><<<dim3(NPTS / GBM, 2), 256>>>(
        features, Wsc, pSC, 64, 256, nullptr, psum + 3 * 256, psq + 3 * 256);
    // 5: layer-2 MMA (BN1+lrelu fused; BN1 finalize inline; 2 N-halves)
    gemm_mma_kernel<256, 1><<<dim3(ROWS / 128, 2), 256, SMEM_MMA>>>(
        p1, pW2t, p2, g1, b1);
    // 6: final epilogue (BN2 + BN_sc finalize inline)
    final_kernel<<<NPTS * 64 / 256, 256>>>(out, g2, b2, gsc, bsc);
}

// round 9
// speedup vs baseline: 1.3426x; 1.0871x over previous
#include <cuda_runtime.h>
#include <cuda_fp16.h>
#include <math.h>
#include <cstdint>

// ---------------------------------------------------------------------------
// Problem constants
// ---------------------------------------------------------------------------
#define NB   32
#define PP   1024
#define C0   64
#define KNN  16
#define NPTS (NB * PP)       // 32768
#define ROWS (NPTS * KNN)    // 524288
#define LRELU_ALPHA 0.1f
#define BN_EPS 1e-3f

// ---------------------------------------------------------------------------
// Static device scratch
// ---------------------------------------------------------------------------
__device__ __half d_Ah [NPTS * 128];     // features @ (W0[:64]-W0[64:])  (fp16)
__device__ __half d_Bh [NPTS * 128];     // features @ W0[64:]            (fp16)
__device__ float  d_SC [NPTS * 256];     // features @ Wsc (pre-BN, fp32)
__device__ __half d_y1 [ROWS * 128];     // y1 (pre-BN, fp16)
__device__ __half d_y2 [(size_t)ROWS * 256];  // y2 (pre-BN, fp16)
__device__ int    d_idx [ROWS];
__device__ uint32_t d_W1t[128 * 64];     // W1 as [n][kw] packed half2
__device__ uint32_t d_W2t[256 * 64];     // W2 as [n][kw] packed half2
__device__ float  d_sum  [4 * 256];
__device__ float  d_sumsq[4 * 256];

__device__ __forceinline__ void mma_f16(float* d, const uint32_t* a, const uint32_t* b) {
    asm volatile(
        "mma.sync.aligned.m16n8k16.row.col.f32.f16.f16.f32 "
        "{%0,%1,%2,%3}, {%4,%5,%6,%7}, {%8,%9}, {%0,%1,%2,%3};"
        : "+f"(d[0]), "+f"(d[1]), "+f"(d[2]), "+f"(d[3])
        : "r"(a[0]), "r"(a[1]), "r"(a[2]), "r"(a[3]), "r"(b[0]), "r"(b[1]));
}
__device__ __forceinline__ void ldmatrix_x4(uint32_t* r, uint32_t addr) {
    asm volatile("ldmatrix.sync.aligned.m8n8.x4.shared.b16 {%0,%1,%2,%3}, [%4];"
                 : "=r"(r[0]), "=r"(r[1]), "=r"(r[2]), "=r"(r[3]) : "r"(addr));
}
__device__ __forceinline__ uint32_t smem_u32(const void* p) {
    uint32_t a;
    asm("{ .reg .u64 t; cvta.to.shared.u64 t, %1; cvt.u32.u64 %0, t; }" : "=r"(a) : "l"(p));
    return a;
}
__device__ __forceinline__ uint32_t pack_h2(float lo, float hi) {
    __half2 h = __floats2half2_rn(lo, hi);
    return *(uint32_t*)&h;
}
__device__ __forceinline__ float lrelu(float x) {
    return x > 0.f ? x : LRELU_ALPHA * x;
}

// ---------------------------------------------------------------------------
// MEGA setup kernel: 1152 blocks x 256 thr.
//  blocks [0,128):    KNN (+ stats zero / W1t / W2t side duties on blocks 0-3)
//  blocks [128,640):  dual GEMM  A = f@(W0lo-W0hi) (sub<256) / B = f@W0hi
//  blocks [640,1152): shortcut GEMM SC = f@Wsc (two 128-col halves), fp32 out
// ---------------------------------------------------------------------------
__global__ void __launch_bounds__(256) mega_kernel(
    const float* __restrict__ pts, const float* __restrict__ feat,
    const float* __restrict__ W0,  const float* __restrict__ Wsc,
    const float* __restrict__ W1,  const float* __restrict__ W2) {
    __shared__ float sbuf[3072];   // knn: sx/sy/sz ; gemm: As(1024)+Bs(1024)
    const int bid = blockIdx.x;
    const int tid = threadIdx.x;

    if (bid < 128) {
        // ---- side duties -------------------------------------------------
        if (bid == 0) {
            for (int i = tid; i < 1024; i += 256) { d_sum[i] = 0.f; d_sumsq[i] = 0.f; }
        } else if (bid == 1) {
            for (int t = tid; t < 128 * 64; t += 256) {
                int n = t >> 6, kw = t & 63;
                d_W1t[t] = pack_h2(W1[(size_t)(2 * kw) * 128 + n],
                                   W1[(size_t)(2 * kw + 1) * 128 + n]);
            }
        } else if (bid <= 3) {
            int base = (bid - 2) * 8192;
            for (int i = tid; i < 8192; i += 256) {
                int t = base + i;
                int n = t >> 6, kw = t & 63;
                d_W2t[t] = pack_h2(W2[(size_t)(2 * kw) * 256 + n],
                                   W2[(size_t)(2 * kw + 1) * 256 + n]);
            }
        }
        // ---- knn ---------------------------------------------------------
        float* sx = sbuf;
        float* sy = sbuf + 1024;
        float* sz = sbuf + 2048;
        int n = bid >> 2;
        int p = ((bid & 3) << 8) + tid;
        const float* base = pts + (size_t)n * PP * 3;
        for (int i = tid; i < PP; i += 256) {
            sx[i] = base[i * 3 + 0];
            sy[i] = base[i * 3 + 1];
            sz[i] = base[i * 3 + 2];
        }
        __syncthreads();
        float qx = sx[p], qy = sy[p], qz = sz[p];
        float bd[KNN]; int bi[KNN];
#pragma unroll
        for (int i = 0; i < KNN; i++) { bd[i] = 3.0e38f; bi[i] = 0; }
        for (int q = 0; q < PP; q++) {
            float dx = sx[q] - qx, dy = sy[q] - qy, dz = sz[q] - qz;
            float d = dx * dx + dy * dy + dz * dz;
            if (q == p) continue;
            if (d < bd[KNN - 1]) {
                int j = KNN - 1;
                while (j > 0 && bd[j - 1] > d) { bd[j] = bd[j - 1]; bi[j] = bi[j - 1]; j--; }
                bd[j] = d; bi[j] = q;
            }
        }
        int ob = (n * PP + p) * KNN;
        for (int k = 0; k < KNN; k++) d_idx[ob + k] = bi[k];
        return;
    }

    // ---- GEMM branches (Kc=64) ------------------------------------------
    const bool dual = bid < 640;
    const int sub = dual ? bid - 128 : bid - 640;
    const int rowBlock = sub & 255;
    const int ysel = sub >> 8;          // dual: 0=A,1=B ; SC: col half
    float* As = sbuf;                   // [8][128]
    float* Bs = sbuf + 1024;            // [8][128]
    const int rowBase = rowBlock * 128;
    const int tx = tid & 15, ty = tid >> 4;
    float acc[8][8];
#pragma unroll
    for (int i = 0; i < 8; i++)
#pragma unroll
        for (int j = 0; j < 8; j++) acc[i][j] = 0.f;
    const int a_row = tid >> 1, a_k4 = (tid & 1) * 4;
    const int b_k = tid >> 5, b_n = (tid & 31) * 4;
#pragma unroll
    for (int k0 = 0; k0 < 64; k0 += 8) {
        float4 av = *(const float4*)&feat[(size_t)(rowBase + a_row) * 64 + k0 + a_k4];
        As[(a_k4 + 0) * 128 + a_row] = av.x;
        As[(a_k4 + 1) * 128 + a_row] = av.y;
        As[(a_k4 + 2) * 128 + a_row] = av.z;
        As[(a_k4 + 3) * 128 + a_row] = av.w;
        float4 bv;
        if (dual) {
            float4 bhi = *(const float4*)&W0[(size_t)(64 + k0 + b_k) * 128 + b_n];
            if (ysel == 0) {
                float4 blo = *(const float4*)&W0[(size_t)(k0 + b_k) * 128 + b_n];
                bv.x = blo.x - bhi.x; bv.y = blo.y - bhi.y;
                bv.z = blo.z - bhi.z; bv.w = blo.w - bhi.w;
            } else bv = bhi;
        } else {
            bv = *(const float4*)&Wsc[(size_t)(k0 + b_k) * 256 + ysel * 128 + b_n];
        }
        *(float4*)&Bs[b_k * 128 + b_n] = bv;
        __syncthreads();
#pragma unroll
        for (int kk = 0; kk < 8; kk++) {
            float4 a0 = *(const float4*)&As[kk * 128 + ty * 8];
            float4 a1 = *(const float4*)&As[kk * 128 + ty * 8 + 4];
            float4 b0 = *(const float4*)&Bs[kk * 128 + tx * 8];
            float4 b1 = *(const float4*)&Bs[kk * 128 + tx * 8 + 4];
            float a[8] = {a0.x, a0.y, a0.z, a0.w, a1.x, a1.y, a1.z, a1.w};
            float b[8] = {b0.x, b0.y, b0.z, b0.w, b1.x, b1.y, b1.z, b1.w};
#pragma unroll
            for (int i = 0; i < 8; i++)
#pragma unroll
                for (int j = 0; j < 8; j++) acc[i][j] += a[i] * b[j];
        }
        __syncthreads();
    }
    if (dual) {
        __half* Yh = ysel ? d_Bh : d_Ah;
#pragma unroll
        for (int i = 0; i < 8; i++) {
            int row = rowBase + ty * 8 + i;
            uint4 v;
            v.x = pack_h2(acc[i][0], acc[i][1]);
            v.y = pack_h2(acc[i][2], acc[i][3]);
            v.z = pack_h2(acc[i][4], acc[i][5]);
            v.w = pack_h2(acc[i][6], acc[i][7]);
            *(uint4*)&Yh[(size_t)row * 128 + tx * 8] = v;
        }
    } else {
#pragma unroll
        for (int i = 0; i < 8; i++) {
            int row = rowBase + ty * 8 + i;
            float4 c0 = {acc[i][0], acc[i][1], acc[i][2], acc[i][3]};
            float4 c1 = {acc[i][4], acc[i][5], acc[i][6], acc[i][7]};
            *(float4*)&d_SC[(size_t)row * 256 + ysel * 128 + tx * 8]     = c0;
            *(float4*)&d_SC[(size_t)row * 256 + ysel * 128 + tx * 8 + 4] = c1;
        }
    }
}

// ---------------------------------------------------------------------------
// Stats kernel: blocks [0,2048) layer-0 virtual-y0 stats (fp16 A/B + idx);
//               blocks [2048,2560) shortcut SC stats (layer 3).
// ---------------------------------------------------------------------------
__global__ void __launch_bounds__(256) stats_kernel() {
    if (blockIdx.x < 2048) {
        const uint4* A4 = (const uint4*)d_Ah;
        const uint4* B4 = (const uint4*)d_Bh;
        __shared__ float ssum[128], ssq[128];
        if (threadIdx.x < 128) { ssum[threadIdx.x] = 0.f; ssq[threadIdx.x] = 0.f; }
        __syncthreads();
        const int start = blockIdx.x * 256 + threadIdx.x;
        const int c8 = start & 15;
        float s[8], q[8];
#pragma unroll
        for (int j = 0; j < 8; j++) { s[j] = 0.f; q[j] = 0.f; }
#pragma unroll 4
        for (int i = 0; i < 16; i++) {
            int e = start + i * 524288;
            int r = e >> 4, cc = e & 15;
            int np = r >> 4, n = r >> 14;
            int id = __ldg(&d_idx[r]);
            uint4 a = A4[(size_t)np * 16 + cc];
            uint4 b = B4[((size_t)n * 1024 + id) * 16 + cc];
            uint32_t aw[4] = {a.x, a.y, a.z, a.w};
            uint32_t bw[4] = {b.x, b.y, b.z, b.w};
#pragma unroll
            for (int j = 0; j < 4; j++) {
                float2 fa = __half22float2(*(__half2*)&aw[j]);
                float2 fb = __half22float2(*(__half2*)&bw[j]);
                float y0 = fa.x + fb.x, y1 = fa.y + fb.y;
                s[j * 2]     += y0; q[j * 2]     += y0 * y0;
                s[j * 2 + 1] += y1; q[j * 2 + 1] += y1 * y1;
            }
        }
#pragma unroll
        for (int j = 0; j < 8; j++) {
            atomicAdd(&ssum[c8 * 8 + j], s[j]);
            atomicAdd(&ssq [c8 * 8 + j], q[j]);
        }
        __syncthreads();
        if (threadIdx.x < 128) {
            atomicAdd(&d_sum  [threadIdx.x], ssum[threadIdx.x]);
            atomicAdd(&d_sumsq[threadIdx.x], ssq[threadIdx.x]);
        }
    } else {
        int b = blockIdx.x - 2048;            // 0..511 -> 64 rows each
        int c = threadIdx.x;                  // channel
        const float* base = d_SC + (size_t)b * 64 * 256 + c;
        float s = 0.f, q = 0.f;
#pragma unroll 8
        for (int r = 0; r < 64; r++) {
            float v = base[(size_t)r * 256];
            s += v; q += v * v;
        }
        atomicAdd(&d_sum  [3 * 256 + c], s);
        atomicAdd(&d_sumsq[3 * 256 + c], q);
    }
}

// ---------------------------------------------------------------------------
// fp16 mma GEMM with ldmatrix: BM=128, K=128 one-shot, 256 thr (8 warps 4x2),
// occ 2. N_TOT/128 column halves processed serially, A produced ONCE.
// MODE 0: A = lrelu(BN0(gather Ah+Bh)), Y = y1 [ROWS,128]
// MODE 1: A = lrelu(BN1(y1)),           Y = y2 [ROWS,256]
// BN(layer_in) finalize inlined; output BN stats accumulated in epilogue.
// ---------------------------------------------------------------------------
#define KW 68
template <int N_TOT, int MODE>
__global__ void __launch_bounds__(256, 2) gemm_mma_kernel(
    const __half* __restrict__ Xin, const uint32_t* __restrict__ Wt,
    __half* __restrict__ Y, const float* __restrict__ g, const float* __restrict__ b) {
    constexpr int LAYER_IN  = MODE;
    constexpr int LAYER_OUT = MODE + 1;
    constexpr int NH = N_TOT / 128;
    extern __shared__ char smem_raw[];
    uint32_t* As = (uint32_t*)smem_raw;                    // [128][KW]
    uint32_t* Bs = As + 128 * KW;                          // [N_TOT][KW]
    float*  ssum = (float*)(Bs + N_TOT * KW);              // [N_TOT]
    float*  ssq  = ssum + N_TOT;                           // [N_TOT]
    float*  scs  = ssq + N_TOT;                            // [128]
    float*  shs  = scs + 128;                              // [128]

    const int tid = threadIdx.x;
    const int wid = tid >> 5;
    const int lane = tid & 31;
    const int gid = lane >> 2;
    const int tg  = lane & 3;
    const int warpRow = wid & 3;
    const int warpCol = wid >> 2;
    const int tileBase = blockIdx.x * 128;

    // inline finalize of BN(layer_in)
    if (tid < 128) {
        float mean = d_sum[LAYER_IN * 256 + tid] * (1.0f / (float)ROWS);
        float var  = d_sumsq[LAYER_IN * 256 + tid] * (1.0f / (float)ROWS) - mean * mean;
        float sc = g[tid] * rsqrtf(var + BN_EPS);
        scs[tid] = sc;
        shs[tid] = b[tid] - mean * sc;
    }
    for (int c2 = tid; c2 < N_TOT; c2 += 256) { ssum[c2] = 0.f; ssq[c2] = 0.f; }
    __syncthreads();

    // ---- B tile: packed copy from pre-transposed Wt ------------------------
    {
        const uint4* src = (const uint4*)Wt;
#pragma unroll
        for (int i = 0; i < N_TOT / 16; i++) {
            int e4 = tid + i * 256;
            int n = e4 >> 4, kw4 = e4 & 15;
            *(uint4*)&Bs[n * KW + kw4 * 4] = src[e4];
        }
    }

    // ---- A tile (fused gather/BN/lrelu producer, fp16 inputs) --------------
    int ids[8];
    if (MODE == 0) {
#pragma unroll
        for (int i = 0; i < 8; i++) {
            int r = (tid + i * 256) >> 4;
            ids[i] = __ldg(&d_idx[tileBase + r]);
        }
    }
#pragma unroll
    for (int i = 0; i < 8; i++) {
        int e = tid + i * 256;
        int r = e >> 4, cw = e & 15;
        int R = tileBase + r;
        float x[8];
        if (MODE == 0) {
            int np = R >> 4, n = R >> 14;
            uint4 ha = ((const uint4*)d_Ah)[(size_t)np * 16 + cw];
            uint4 hb = ((const uint4*)d_Bh)[((size_t)n * 1024 + ids[i]) * 16 + cw];
            uint32_t aw[4] = {ha.x, ha.y, ha.z, ha.w};
            uint32_t bw[4] = {hb.x, hb.y, hb.z, hb.w};
#pragma unroll
            for (int j = 0; j < 4; j++) {
                float2 fa = __half22float2(*(__half2*)&aw[j]);
                float2 fb = __half22float2(*(__half2*)&bw[j]);
                x[j * 2] = fa.x + fb.x; x[j * 2 + 1] = fa.y + fb.y;
            }
        } else {
            uint4 h = ((const uint4*)&Xin[(size_t)R * 128])[cw];
            uint32_t hw[4] = {h.x, h.y, h.z, h.w};
#pragma unroll
            for (int j = 0; j < 4; j++) {
                float2 f = __half22float2(*(__half2*)&hw[j]);
                x[j * 2] = f.x; x[j * 2 + 1] = f.y;
            }
        }
        const float* sc = &scs[cw * 8];
        const float* sh = &shs[cw * 8];
        float y[8];
#pragma unroll
        for (int j = 0; j < 8; j++) y[j] = lrelu(x[j] * sc[j] + sh[j]);
        uint4 v;
        v.x = pack_h2(y[0], y[1]); v.y = pack_h2(y[2], y[3]);
        v.z = pack_h2(y[4], y[5]); v.w = pack_h2(y[6], y[7]);
        *(uint4*)&As[r * KW + cw * 4] = v;
    }
    __syncthreads();

    // ---- ldmatrix base addresses (k-step 0), advance 32B per k-step --------
    const int t8 = lane >> 3, r8 = lane & 7;
    uint32_t aAddr[2], bAddr[4];
#pragma unroll
    for (int mi = 0; mi < 2; mi++) {
        int row = warpRow * 32 + mi * 16 + (t8 & 1) * 8 + r8;
        aAddr[mi] = smem_u32(&As[row * KW + (t8 >> 1) * 4]);
    }
#pragma unroll
    for (int nj = 0; nj < 4; nj++) {
        int row = warpCol * 64 + nj * 16 + (t8 >> 1) * 8 + r8;
        bAddr[nj] = smem_u32(&Bs[row * KW + (t8 & 1) * 4]);
    }

    // ---- loop over N halves: MMA + epilogue --------------------------------
#pragma unroll
    for (int h = 0; h < NH; h++) {
        const uint32_t bOff = (uint32_t)h * 128u * KW * 4u;
        float c[2][8][4];
#pragma unroll
        for (int mi = 0; mi < 2; mi++)
#pragma unroll
            for (int ni = 0; ni < 8; ni++)
#pragma unroll
                for (int j = 0; j < 4; j++) c[mi][ni][j] = 0.f;

#pragma unroll
        for (int k0 = 0; k0 < 8; k0++) {
            uint32_t af[2][4], bf[4][4];
#pragma unroll
            for (int mi = 0; mi < 2; mi++) ldmatrix_x4(af[mi], aAddr[mi] + k0 * 32);
#pragma unroll
            for (int nj = 0; nj < 4; nj++) ldmatrix_x4(bf[nj], bAddr[nj] + bOff + k0 * 32);
#pragma unroll
            for (int mi = 0; mi < 2; mi++)
#pragma unroll
                for (int nj = 0; nj < 4; nj++) {
                    mma_f16(c[mi][nj * 2],     af[mi], &bf[nj][0]);
                    mma_f16(c[mi][nj * 2 + 1], af[mi], &bf[nj][2]);
                }
        }

        // store fp16 y + stats
#pragma unroll
        for (int mi = 0; mi < 2; mi++) {
            size_t r0 = (size_t)tileBase + warpRow * 32 + mi * 16 + gid;
#pragma unroll
            for (int ni = 0; ni < 8; ni++) {
                int col = h * 128 + warpCol * 64 + ni * 8 + tg * 2;
                __half2 v0 = __floats2half2_rn(c[mi][ni][0], c[mi][ni][1]);
                __half2 v1 = __floats2half2_rn(c[mi][ni][2], c[mi][ni][3]);
                *(__half2*)&Y[ r0      * N_TOT + col] = v0;
                *(__half2*)&Y[(r0 + 8) * N_TOT + col] = v1;
            }
        }
#pragma unroll
        for (int ni = 0; ni < 8; ni++) {
#pragma unroll
            for (int j = 0; j < 2; j++) {
                float s = c[0][ni][j] + c[0][ni][j + 2] + c[1][ni][j] + c[1][ni][j + 2];
                float q = c[0][ni][j]     * c[0][ni][j]
                        + c[0][ni][j + 2] * c[0][ni][j + 2]
                        + c[1][ni][j]     * c[1][ni][j]
                        + c[1][ni][j + 2] * c[1][ni][j + 2];
#pragma unroll
                for (int m = 16; m >= 4; m >>= 1) {
                    s += __shfl_xor_sync(0xffffffffu, s, m);
                    q += __shfl_xor_sync(0xffffffffu, q, m);
                }
                if (lane < 4) {
                    int cch = h * 128 + warpCol * 64 + ni * 8 + tg * 2 + j;
                    atomicAdd(&ssum[cch], s);
                    atomicAdd(&ssq [cch], q);
                }
            }
        }
    }
    __syncthreads();
    for (int c2 = tid; c2 < N_TOT; c2 += 256) {
        atomicAdd(&d_sum  [LAYER_OUT * 256 + c2], ssum[c2]);
        atomicAdd(&d_sumsq[LAYER_OUT * 256 + c2], ssq[c2]);
    }
}

// ---------------------------------------------------------------------------
// Final epilogue with inline finalize of BN2 (layer 2) and BN_sc (layer 3):
// out = lrelu( BN_sc(SC) + mean_k lrelu(BN2(y2)) )
// ---------------------------------------------------------------------------
__global__ void __launch_bounds__(256) final_kernel(
    float* __restrict__ out,
    const float* __restrict__ g2, const float* __restrict__ b2,
    const float* __restrict__ gsc, const float* __restrict__ bsc) {
    __shared__ float s2s[256], h2s[256], s3s[256], h3s[256];
    {
        int c = threadIdx.x;
        float mean2 = d_sum[2 * 256 + c] * (1.0f / (float)ROWS);
        float var2  = d_sumsq[2 * 256 + c] * (1.0f / (float)ROWS) - mean2 * mean2;
        float sc2 = g2[c] * rsqrtf(var2 + BN_EPS);
        s2s[c] = sc2; h2s[c] = b2[c] - mean2 * sc2;
        float mean3 = d_sum[3 * 256 + c] * (1.0f / (float)NPTS);
        float var3  = d_sumsq[3 * 256 + c] * (1.0f / (float)NPTS) - mean3 * mean3;
        float sc3 = gsc[c] * rsqrtf(var3 + BN_EPS);
        s3s[c] = sc3; h3s[c] = bsc[c] - mean3 * sc3;
    }
    __syncthreads();
    int t = blockIdx.x * blockDim.x + threadIdx.x;
    int np = t >> 6, c4 = t & 63;
    float4 s2 = *(const float4*)&s2s[c4 * 4];
    float4 h2 = *(const float4*)&h2s[c4 * 4];
    float4 s3 = *(const float4*)&s3s[c4 * 4];
    float4 h3 = *(const float4*)&h3s[c4 * 4];
    const uint2* Y2 = (const uint2*)d_y2;
    size_t base = (size_t)np * 16 * 64 + c4;
    float ax = 0, ay = 0, az = 0, aw = 0;
#pragma unroll
    for (int k = 0; k < KNN; k++) {
        uint2 hv = Y2[base + (size_t)k * 64];
        float2 f01 = __half22float2(*(__half2*)&hv.x);
        float2 f23 = __half22float2(*(__half2*)&hv.y);
        ax += lrelu(f01.x * s2.x + h2.x);
        ay += lrelu(f01.y * s2.y + h2.y);
        az += lrelu(f23.x * s2.z + h2.z);
        aw += lrelu(f23.y * s2.w + h2.w);
    }
    const float inv = 1.0f / (float)KNN;
    float4 s = ((const float4*)d_SC)[np * 64 + c4];
    float4 o;
    o.x = lrelu(s.x * s3.x + h3.x + ax * inv);
    o.y = lrelu(s.y * s3.y + h3.y + ay * inv);
    o.z = lrelu(s.z * s3.z + h3.z + az * inv);
    o.w = lrelu(s.w * s3.w + h3.w + aw * inv);
    ((float4*)out)[t] = o;
}

// ---------------------------------------------------------------------------
// Launch (5 launches; mma2 at idx 3 -> ncu abs index 5 gets profiled)
// ---------------------------------------------------------------------------
extern "C" void kernel_launch(void* const* d_in, const int* in_sizes, int n_in,
                              void* d_out, int out_size) {
    const float* points   = (const float*)d_in[0];
    const float* features = (const float*)d_in[1];
    const float* W0  = (const float*)d_in[2];
    const float* g0  = (const float*)d_in[3];
    const float* b0  = (const float*)d_in[4];
    const float* W1  = (const float*)d_in[5];
    const float* g1  = (const float*)d_in[6];
    const float* b1  = (const float*)d_in[7];
    const float* W2  = (const float*)d_in[8];
    const float* g2  = (const float*)d_in[9];
    const float* b2  = (const float*)d_in[10];
    const float* Wsc = (const float*)d_in[11];
    const float* gsc = (const float*)d_in[12];
    const float* bsc = (const float*)d_in[13];
    float* out = (float*)d_out;

    __half *p1, *p2;
    uint32_t *pW1t, *pW2t;
    cudaGetSymbolAddress((void**)&p1,  d_y1);
    cudaGetSymbolAddress((void**)&p2,  d_y2);
    cudaGetSymbolAddress((void**)&pW1t, d_W1t);
    cudaGetSymbolAddress((void**)&pW2t, d_W2t);

    constexpr int SMEM_MMA1 = (128 * KW + 128 * KW) * 4 + (2 * 128 + 2 * 128) * 4;
    constexpr int SMEM_MMA2 = (128 * KW + 256 * KW) * 4 + (2 * 256 + 2 * 128) * 4;
    cudaFuncSetAttribute(gemm_mma_kernel<128, 0>,
                         cudaFuncAttributeMaxDynamicSharedMemorySize, SMEM_MMA1);
    cudaFuncSetAttribute(gemm_mma_kernel<256, 1>,
                         cudaFuncAttributeMaxDynamicSharedMemorySize, SMEM_MMA2);

    // 0: mega setup (knn + stats zero + W transposes + dual GEMM + SC GEMM)
    mega_kernel<<<1152, 256>>>(points, features, W0, Wsc, W1, W2);
    // 1: layer-0 virtual-y0 stats + SC stats
    stats_kernel<<<2560, 256>>>();
    // 2: layer-1 MMA (gather+BN0+lrelu fused; BN0 finalize inline)
    gemm_mma_kernel<128, 0><<<ROWS / 128, 256, SMEM_MMA1>>>(nullptr, pW1t, p1, g0, b0);
    // 3: layer-2 MMA (BN1+lrelu fused; both N-halves, A produced once) [PROFILED]
    gemm_mma_kernel<256, 1><<<ROWS / 128, 256, SMEM_MMA2>>>(p1, pW2t, p2, g1, b1);
    // 4: final epilogue (BN2 + BN_sc finalize inline)
    final_kernel<<<NPTS * 64 / 256, 256>>>(out, g2, b2, gsc, bsc);
}